// round 3
// baseline (speedup 1.0000x reference)
#include <cuda_runtime.h>

#define CC 256
#define LL 8192
#define BB 8
#define CR 64
#define GC 16
#define KK 7
#define GK 112          // G*K = 16*7
#define TILE 64
#define SX_W 72         // padded halo row width (70 used, col 1..70; center t at col 4+t)

// 64 MB scratch for normalized activations (B, C, L)
__device__ float g_outn[BB * CC * LL];

// ---------- packed f32x2 helpers (FFMA2 path: 128 FMA/cyc/SM vs 64 for FFMA-3reg) ----------
__device__ __forceinline__ unsigned long long pk2(float v) {
    unsigned long long r;
    unsigned u = __float_as_uint(v);
    asm("mov.b64 %0, {%1, %1};" : "=l"(r) : "r"(u));
    return r;
}
__device__ __forceinline__ void fma2(unsigned long long& d, unsigned long long a, unsigned long long b) {
    asm("fma.rn.f32x2 %0, %1, %2, %0;" : "+l"(d) : "l"(a), "l"(b));
}
__device__ __forceinline__ float2 up2(unsigned long long v) {
    unsigned lo, hi;
    asm("mov.b64 {%0, %1}, %2;" : "=r"(lo), "=r"(hi) : "l"(v));
    return make_float2(__uint_as_float(lo), __uint_as_float(hi));
}

// ============================================================================
// Kernel 1: fused kernel-generation + involution + PReLU + LayerNorm
// grid (L/TILE=128, B=8), 256 threads, ~208KB dynamic smem, 1 CTA/SM
// ============================================================================
#define SMEM_FLOATS (256*SX_W + GK*64 + 64*64 + GK*64 + 256*64 + 128)
#define SMEM_BYTES  (SMEM_FLOATS * 4)

extern __shared__ float smem[];

__global__ void __launch_bounds__(256, 1) front_kernel(
    const float* __restrict__ x, const float* __restrict__ w_reduce,
    const float* __restrict__ w_span, const float* __restrict__ prelu_a,
    const float* __restrict__ ln_gamma, const float* __restrict__ ln_beta)
{
    float* sx    = smem;                  // [256][72]   x halo tile
    float* sspan = sx + 256 * SX_W;       // [112][64]   w_span
    float* sh    = sspan + GK * 64;       // [64][64]    h = relu(w_reduce @ x)
    float* sker  = sh + 64 * 64;          // [112][64]   involution kernels
    float* sout  = sker + GK * 64;        // [256][64]   pre-LN activations
    float* smu   = sout + 256 * 64;       // [64]
    float* srs   = smu + 64;              // [64]

    const int tid = threadIdx.x;
    const int b   = blockIdx.y;
    const int l0  = blockIdx.x * TILE;
    const float* xb = x + (size_t)b * CC * LL;

    // ---- load x halo tile (zero-padded at sequence edges) ----
    for (int idx = tid; idx < 256 * 70; idx += 256) {
        int c = idx / 70, j = idx - c * 70;
        int l = l0 - 3 + j;
        sx[c * SX_W + 1 + j] = (l >= 0 && l < LL) ? xb[c * LL + l] : 0.f;
    }
    // ---- load w_span ----
    for (int idx = tid; idx < GK * 64; idx += 256) sspan[idx] = w_span[idx];
    __syncthreads();

    const int t4 = tid & 15;      // 16 t-groups of 4 positions
    const int q  = tid >> 4;      // 16 row-groups
    const int tb = t4 << 2;       // base t within tile

    // ---- h[r][t] = relu(sum_c w_reduce[r][c] * x[c][t]),  r in 0..63 ----
    #pragma unroll
    for (int i = 0; i < 4; i++) {
        int r = q + 16 * i;
        const float* wr = w_reduce + r * 256;
        unsigned long long acc0 = 0ull, acc1 = 0ull;
        #pragma unroll 8
        for (int c = 0; c < 256; c++) {
            unsigned long long wd = pk2(__ldg(wr + c));
            const float* p = sx + c * SX_W + 4 + tb;
            fma2(acc0, wd, *(const unsigned long long*)p);
            fma2(acc1, wd, *(const unsigned long long*)(p + 2));
        }
        float2 v0 = up2(acc0), v1 = up2(acc1);
        float* o = sh + r * 64 + tb;
        o[0] = fmaxf(v0.x, 0.f); o[1] = fmaxf(v0.y, 0.f);
        o[2] = fmaxf(v1.x, 0.f); o[3] = fmaxf(v1.y, 0.f);
    }
    __syncthreads();

    // ---- ker[k][t] = sum_r w_span[k][r] * h[r][t],  k in 0..111 ----
    #pragma unroll
    for (int i = 0; i < 7; i++) {
        int k = q + 16 * i;
        const float* wk = sspan + k * 64;
        unsigned long long acc0 = 0ull, acc1 = 0ull;
        #pragma unroll 8
        for (int r = 0; r < 64; r++) {
            unsigned long long wd = pk2(wk[r]);
            const float* p = sh + r * 64 + tb;
            fma2(acc0, wd, *(const unsigned long long*)p);
            fma2(acc1, wd, *(const unsigned long long*)(p + 2));
        }
        float2 v0 = up2(acc0), v1 = up2(acc1);
        float* o = sker + k * 64 + tb;
        o[0] = v0.x; o[1] = v0.y; o[2] = v1.x; o[3] = v1.y;
    }
    __syncthreads();

    // ---- involution (weighted window sum over K=7) + PReLU ----
    const float al = prelu_a[0];
    #pragma unroll
    for (int i = 0; i < 16; i++) {
        int c  = q + 16 * i;
        int g7 = (c >> 4) * KK;
        float a0 = 0.f, a1 = 0.f, a2 = 0.f, a3 = 0.f;
        const float* xr = sx + c * SX_W + 1 + tb;   // xr[j+k] = x[l0+tb+j + k-3]
        #pragma unroll
        for (int k = 0; k < KK; k++) {
            float4 kv = *(const float4*)(sker + (g7 + k) * 64 + tb);
            a0 += kv.x * xr[k];
            a1 += kv.y * xr[k + 1];
            a2 += kv.z * xr[k + 2];
            a3 += kv.w * xr[k + 3];
        }
        float* o = sout + c * 64 + tb;
        o[0] = a0 >= 0.f ? a0 : al * a0;
        o[1] = a1 >= 0.f ? a1 : al * a1;
        o[2] = a2 >= 0.f ? a2 : al * a2;
        o[3] = a3 >= 0.f ? a3 : al * a3;
    }
    __syncthreads();

    // ---- LayerNorm statistics over channels, per position ----
    {
        int col = tid >> 2, part = tid & 3;   // 4 threads per column
        float s = 0.f, s2 = 0.f;
        const float* p = sout + part * 64 * 64 + col;
        #pragma unroll 8
        for (int c = 0; c < 64; c++) { float v = p[c * 64]; s += v; s2 += v * v; }
        s  += __shfl_xor_sync(0xffffffffu, s, 1);
        s2 += __shfl_xor_sync(0xffffffffu, s2, 1);
        s  += __shfl_xor_sync(0xffffffffu, s, 2);
        s2 += __shfl_xor_sync(0xffffffffu, s2, 2);
        if (part == 0) {
            float mu  = s * (1.f / 256.f);
            float var = s2 * (1.f / 256.f) - mu * mu;
            smu[col] = mu;
            srs[col] = rsqrtf(var + 1e-5f);
        }
    }
    __syncthreads();

    // ---- normalize + affine, write outn to scratch ----
    float* ob = g_outn + (size_t)b * CC * LL + l0;
    for (int idx = tid; idx < 256 * 64; idx += 256) {
        int c = idx >> 6, t = idx & 63;
        float v = (sout[idx] - smu[t]) * srs[t];
        ob[c * LL + t] = v * __ldg(ln_gamma + c) + __ldg(ln_beta + c);
    }
}

// ============================================================================
// Kernel 2: fused main/skip GEMM + residual.
// out[512, 65536] = [w_main; w_skip] @ outn ; main half += x.
// Block tile 128x128, K-chunk 16, 8x8 thread tiles, packed-f32x2 accumulate.
// grid (B*L/128 = 512, 4), 256 threads.
// ============================================================================
__global__ void __launch_bounds__(256, 2) gemm_kernel(
    const float* __restrict__ x, const float* __restrict__ w_main,
    const float* __restrict__ w_skip, float* __restrict__ out)
{
    __shared__ float As[2][16][132];   // transposed W tile, padded
    __shared__ float Bs[2][16][128];   // outn tile

    const int tid = threadIdx.x;
    const int b   = blockIdx.x >> 6;          // / (L/128)
    const int l0  = (blockIdx.x & 63) << 7;   // * 128
    const int m0  = blockIdx.y << 7;
    const float* W = (m0 < 256) ? (w_main + m0 * 256) : (w_skip + (m0 - 256) * 256);
    const float* Bbase = g_outn + (size_t)b * CC * LL + l0;

    unsigned long long acc[8][4];
    #pragma unroll
    for (int i = 0; i < 8; i++)
        #pragma unroll
        for (int j = 0; j < 4; j++) acc[i][j] = 0ull;

    // ---- prologue: load k-chunk 0 into buffer 0 ----
    #pragma unroll
    for (int it = 0; it < 2; it++) {
        int v  = tid + (it << 8);
        int m  = v >> 2, k0 = (v & 3) << 2;
        float4 ra = *(const float4*)(W + m * 256 + k0);
        As[0][k0 + 0][m] = ra.x; As[0][k0 + 1][m] = ra.y;
        As[0][k0 + 2][m] = ra.z; As[0][k0 + 3][m] = ra.w;
        int k = v >> 5, n0 = (v & 31) << 2;
        *(float4*)&Bs[0][k][n0] = *(const float4*)(Bbase + (size_t)k * LL + n0);
    }
    __syncthreads();

    const int ty = tid >> 4, tx = tid & 15;

    for (int kt = 0; kt < 16; kt++) {
        const int cur = kt & 1;
        float4 ra0, ra1, rb0, rb1;
        if (kt < 15) {
            const int kc = (kt + 1) << 4;
            {
                int v = tid;
                int m = v >> 2, k0 = (v & 3) << 2;
                ra0 = *(const float4*)(W + m * 256 + kc + k0);
                int k = v >> 5, n0 = (v & 31) << 2;
                rb0 = *(const float4*)(Bbase + (size_t)(kc + k) * LL + n0);
            }
            {
                int v = tid + 256;
                int m = v >> 2, k0 = (v & 3) << 2;
                ra1 = *(const float4*)(W + m * 256 + kc + k0);
                int k = v >> 5, n0 = (v & 31) << 2;
                rb1 = *(const float4*)(Bbase + (size_t)(kc + k) * LL + n0);
            }
        }
        #pragma unroll
        for (int k = 0; k < 16; k++) {
            float4 a0 = *(const float4*)&As[cur][k][ty << 3];
            float4 a1 = *(const float4*)&As[cur][k][(ty << 3) + 4];
            const unsigned long long* bp = (const unsigned long long*)&Bs[cur][k][tx << 3];
            unsigned long long b0 = bp[0], b1 = bp[1], b2 = bp[2], b3 = bp[3];
            unsigned long long d;
            d = pk2(a0.x); fma2(acc[0][0], d, b0); fma2(acc[0][1], d, b1); fma2(acc[0][2], d, b2); fma2(acc[0][3], d, b3);
            d = pk2(a0.y); fma2(acc[1][0], d, b0); fma2(acc[1][1], d, b1); fma2(acc[1][2], d, b2); fma2(acc[1][3], d, b3);
            d = pk2(a0.z); fma2(acc[2][0], d, b0); fma2(acc[2][1], d, b1); fma2(acc[2][2], d, b2); fma2(acc[2][3], d, b3);
            d = pk2(a0.w); fma2(acc[3][0], d, b0); fma2(acc[3][1], d, b1); fma2(acc[3][2], d, b2); fma2(acc[3][3], d, b3);
            d = pk2(a1.x); fma2(acc[4][0], d, b0); fma2(acc[4][1], d, b1); fma2(acc[4][2], d, b2); fma2(acc[4][3], d, b3);
            d = pk2(a1.y); fma2(acc[5][0], d, b0); fma2(acc[5][1], d, b1); fma2(acc[5][2], d, b2); fma2(acc[5][3], d, b3);
            d = pk2(a1.z); fma2(acc[6][0], d, b0); fma2(acc[6][1], d, b1); fma2(acc[6][2], d, b2); fma2(acc[6][3], d, b3);
            d = pk2(a1.w); fma2(acc[7][0], d, b0); fma2(acc[7][1], d, b1); fma2(acc[7][2], d, b2); fma2(acc[7][3], d, b3);
        }
        if (kt < 15) {
            __syncthreads();
            const int nxt = cur ^ 1;
            {
                int v = tid;
                int m = v >> 2, k0 = (v & 3) << 2;
                As[nxt][k0 + 0][m] = ra0.x; As[nxt][k0 + 1][m] = ra0.y;
                As[nxt][k0 + 2][m] = ra0.z; As[nxt][k0 + 3][m] = ra0.w;
                int k = v >> 5, n0 = (v & 31) << 2;
                *(float4*)&Bs[nxt][k][n0] = rb0;
            }
            {
                int v = tid + 256;
                int m = v >> 2, k0 = (v & 3) << 2;
                As[nxt][k0 + 0][m] = ra1.x; As[nxt][k0 + 1][m] = ra1.y;
                As[nxt][k0 + 2][m] = ra1.z; As[nxt][k0 + 3][m] = ra1.w;
                int k = v >> 5, n0 = (v & 31) << 2;
                *(float4*)&Bs[nxt][k][n0] = rb1;
            }
            __syncthreads();
        }
    }

    // ---- epilogue: +x residual on main half, write both outputs ----
    const size_t CL = (size_t)CC * LL;
    const int n = l0 + (tx << 3);
    #pragma unroll
    for (int im = 0; im < 8; im++) {
        int m = m0 + (ty << 3) + im;
        float2 p0 = up2(acc[im][0]), p1 = up2(acc[im][1]);
        float2 p2 = up2(acc[im][2]), p3 = up2(acc[im][3]);
        float4 r0 = make_float4(p0.x, p0.y, p1.x, p1.y);
        float4 r1 = make_float4(p2.x, p2.y, p3.x, p3.y);
        float* dst;
        if (m < 256) {
            const float* xr = x + (size_t)b * CL + (size_t)m * LL + n;
            float4 x0 = *(const float4*)xr;
            float4 x1 = *(const float4*)(xr + 4);
            r0.x += x0.x; r0.y += x0.y; r0.z += x0.z; r0.w += x0.w;
            r1.x += x1.x; r1.y += x1.y; r1.z += x1.z; r1.w += x1.w;
            dst = out + (size_t)b * CL + (size_t)m * LL + n;
        } else {
            dst = out + (size_t)BB * CL + (size_t)b * CL + (size_t)(m - 256) * LL + n;
        }
        *(float4*)dst = r0;
        *(float4*)(dst + 4) = r1;
    }
}

// ============================================================================
extern "C" void kernel_launch(void* const* d_in, const int* in_sizes, int n_in,
                              void* d_out, int out_size) {
    const float* x        = (const float*)d_in[0];
    const float* w_reduce = (const float*)d_in[1];
    const float* w_span   = (const float*)d_in[2];
    const float* prelu_a  = (const float*)d_in[3];
    const float* ln_gamma = (const float*)d_in[4];
    const float* ln_beta  = (const float*)d_in[5];
    const float* w_main   = (const float*)d_in[6];
    const float* w_skip   = (const float*)d_in[7];
    float* out = (float*)d_out;

    cudaFuncSetAttribute(front_kernel, cudaFuncAttributeMaxDynamicSharedMemorySize, SMEM_BYTES);

    front_kernel<<<dim3(LL / TILE, BB), 256, SMEM_BYTES>>>(
        x, w_reduce, w_span, prelu_a, ln_gamma, ln_beta);
    gemm_kernel<<<dim3((BB * LL) / 128, 4), 256>>>(x, w_main, w_skip, out);
}

// round 4
// speedup vs baseline: 1.2397x; 1.2397x over previous
#include <cuda_runtime.h>

#define CC 256
#define LL 8192
#define BB 8
#define KK 7
#define GK 112          // G*K = 16*7
#define TILE 64
#define SX_W 72         // padded halo row width

typedef unsigned long long ull;

// ---- device scratch (no allocations allowed) ----
__device__ float g_outn[BB * CC * LL];   // 64 MB normalized activations
__device__ float g_wrT[256 * 64];        // w_reduce transposed [c][r]
__device__ float g_wsT2[64 * 256];       // w_span transposed+duplicated [r][kg*16 + 2i(+1)]

// ---------- packed f32x2 helpers ----------
__device__ __forceinline__ ull pk2(float v) {
    ull r; unsigned u = __float_as_uint(v);
    asm("mov.b64 %0, {%1, %1};" : "=l"(r) : "r"(u));
    return r;
}
__device__ __forceinline__ void fma2(ull& d, ull a, ull b) {
    asm("fma.rn.f32x2 %0, %1, %2, %0;" : "+l"(d) : "l"(a), "l"(b));
}
__device__ __forceinline__ float2 up2(ull v) {
    unsigned lo, hi;
    asm("mov.b64 {%0, %1}, %2;" : "=r"(lo), "=r"(hi) : "l"(v));
    return make_float2(__uint_as_float(lo), __uint_as_float(hi));
}

extern __shared__ float smem_f[];

// ============================================================================
// Kernel 0: one-time weight transpose/duplication (runs every launch; tiny)
// ============================================================================
__global__ void prep_kernel(const float* __restrict__ wr, const float* __restrict__ ws) {
    int tid = blockIdx.x * 256 + threadIdx.x;          // 0..32767
    if (tid < 16384) {
        int c = tid >> 6, r = tid & 63;
        g_wrT[tid] = wr[r * 256 + c];
    } else {
        int i2 = tid - 16384;                          // 0..16383
        int r = i2 >> 8, rem = i2 & 255;
        int kg = rem >> 4, j = rem & 15;
        g_wsT2[i2] = (j < 14) ? ws[(kg * 7 + (j >> 1)) * 64 + r] : 0.f;
    }
}

// ============================================================================
// Kernel 1: fused kernel-gen + involution + PReLU + LayerNorm
// grid (128, 8), 512 threads, 185 KB smem (3-phase aliased union region)
// ============================================================================
#define FR_SMEM_FLOATS (256*SX_W + 64*64 + GK*64 + 16384 + 128)
#define FR_SMEM_BYTES  (FR_SMEM_FLOATS * 4)

__global__ void __launch_bounds__(512, 1) front_kernel(
    const float* __restrict__ x, const float* __restrict__ prelu_a,
    const float* __restrict__ ln_gamma, const float* __restrict__ ln_beta)
{
    float* sx   = smem_f;                 // [256][72] x halo tile
    float* sh   = sx + 256 * SX_W;        // [64][64]
    float* sker = sh + 64 * 64;           // [112][64]
    float* suni = sker + GK * 64;         // 16384: wrT -> wsT2 -> sout
    float* smu  = suni + 16384;           // [64]
    float* srs  = smu + 64;               // [64]

    const int tid = threadIdx.x;
    const int b   = blockIdx.y;
    const int l0  = blockIdx.x * TILE;
    const float* xb = x + (size_t)b * CC * LL;

    // ---- load x halo tile + wrT ----
    for (int idx = tid; idx < 256 * 70; idx += 512) {
        int c = idx / 70, j = idx - c * 70;
        int l = l0 - 3 + j;
        sx[c * SX_W + 1 + j] = (l >= 0 && l < LL) ? xb[c * LL + l] : 0.f;
    }
    for (int i = tid; i < 4096; i += 512)
        ((float4*)suni)[i] = ((const float4*)g_wrT)[i];
    __syncthreads();

    // ---- h[r][t] = relu(Wr @ x): 2r x 4t per thread ----
    {
        const int rh = tid >> 4, r0 = rh << 1;
        const int tq = tid & 15, t0 = tq << 2;
        ull a00 = 0, a01 = 0, a10 = 0, a11 = 0;
        const float* xp = sx + 4 + t0;
        const float* wp = suni + r0;
        #pragma unroll 8
        for (int c = 0; c < 256; c++) {
            ulonglong2 bb = *(const ulonglong2*)(xp + c * SX_W);   // LDS.128
            float2 aw = *(const float2*)(wp + (c << 6));
            ull d0 = pk2(aw.x), d1 = pk2(aw.y);
            fma2(a00, d0, bb.x); fma2(a01, d0, bb.y);
            fma2(a10, d1, bb.x); fma2(a11, d1, bb.y);
        }
        float2 v;
        float* o0 = sh + r0 * 64 + t0;
        float* o1 = o0 + 64;
        v = up2(a00); o0[0] = fmaxf(v.x, 0.f); o0[1] = fmaxf(v.y, 0.f);
        v = up2(a01); o0[2] = fmaxf(v.x, 0.f); o0[3] = fmaxf(v.y, 0.f);
        v = up2(a10); o1[0] = fmaxf(v.x, 0.f); o1[1] = fmaxf(v.y, 0.f);
        v = up2(a11); o1[2] = fmaxf(v.x, 0.f); o1[3] = fmaxf(v.y, 0.f);
    }
    __syncthreads();

    // ---- swap union region: wrT -> wsT2 ----
    for (int i = tid; i < 4096; i += 512)
        ((float4*)suni)[i] = ((const float4*)g_wsT2)[i];
    __syncthreads();

    // ---- ker[k][t] = Ws @ h: 7k x 2t per thread (duplicated weights) ----
    {
        const int kg = tid >> 5;        // 0..15
        const int tp = tid & 31, t2 = tp << 1;
        ull acc[7] = {0, 0, 0, 0, 0, 0, 0};
        const float* hp = sh + t2;
        #pragma unroll 4
        for (int r = 0; r < 64; r++) {
            ull bv = *(const ull*)(hp + (r << 6));
            const ull* w = (const ull*)(suni + (r << 8) + (kg << 4));
            #pragma unroll
            for (int i = 0; i < 7; i++) fma2(acc[i], w[i], bv);
        }
        #pragma unroll
        for (int i = 0; i < 7; i++) {
            float2 v = up2(acc[i]);
            *(float2*)(sker + (kg * 7 + i) * 64 + t2) = v;
        }
    }
    __syncthreads();

    // ---- involution (K=7 weighted window) + PReLU -> sout(=suni) ----
    {
        const float al = prelu_a[0];
        const int q = tid >> 4;            // 0..31
        const int tb = (tid & 15) << 2;
        #pragma unroll
        for (int i = 0; i < 8; i++) {
            int c  = q + 32 * i;
            int g7 = (c >> 4) * KK;
            float a0 = 0.f, a1 = 0.f, a2 = 0.f, a3 = 0.f;
            const float* xr = sx + c * SX_W + 1 + tb;
            #pragma unroll
            for (int k = 0; k < KK; k++) {
                float4 kv = *(const float4*)(sker + (g7 + k) * 64 + tb);
                a0 += kv.x * xr[k];
                a1 += kv.y * xr[k + 1];
                a2 += kv.z * xr[k + 2];
                a3 += kv.w * xr[k + 3];
            }
            float* o = suni + c * 64 + tb;
            o[0] = a0 >= 0.f ? a0 : al * a0;
            o[1] = a1 >= 0.f ? a1 : al * a1;
            o[2] = a2 >= 0.f ? a2 : al * a2;
            o[3] = a3 >= 0.f ? a3 : al * a3;
        }
    }
    __syncthreads();

    // ---- LayerNorm stats per position (8 threads per column) ----
    {
        int col = tid >> 3, part = tid & 7;
        float s = 0.f, s2 = 0.f;
        const float* p = suni + (part << 5) * 64 + col;
        #pragma unroll 8
        for (int cc = 0; cc < 32; cc++) { float v = p[cc * 64]; s += v; s2 += v * v; }
        s  += __shfl_xor_sync(0xffffffffu, s, 1);
        s2 += __shfl_xor_sync(0xffffffffu, s2, 1);
        s  += __shfl_xor_sync(0xffffffffu, s, 2);
        s2 += __shfl_xor_sync(0xffffffffu, s2, 2);
        s  += __shfl_xor_sync(0xffffffffu, s, 4);
        s2 += __shfl_xor_sync(0xffffffffu, s2, 4);
        if (part == 0) {
            float mu  = s * (1.f / 256.f);
            float var = s2 * (1.f / 256.f) - mu * mu;
            smu[col] = mu;
            srs[col] = rsqrtf(var + 1e-5f);
        }
    }
    __syncthreads();

    // ---- normalize + affine, vectorized store to scratch ----
    {
        float* ob = g_outn + (size_t)b * CC * LL + l0;
        #pragma unroll
        for (int it = 0; it < 8; it++) {
            int idx = tid + (it << 9);          // 0..4095
            int c = idx >> 4, tq2 = (idx & 15) << 2;
            float4 v = *(const float4*)(suni + (c << 6) + tq2);
            float4 m = *(const float4*)(smu + tq2);
            float4 r = *(const float4*)(srs + tq2);
            float g = __ldg(ln_gamma + c), be = __ldg(ln_beta + c);
            v.x = (v.x - m.x) * r.x * g + be;
            v.y = (v.y - m.y) * r.y * g + be;
            v.z = (v.z - m.z) * r.z * g + be;
            v.w = (v.w - m.w) * r.w * g + be;
            *(float4*)(ob + (size_t)c * LL + tq2) = v;
        }
    }
}

// ============================================================================
// Kernel 2: fused main/skip GEMM + residual.
// CTA tile 128m x 256n, 256 threads, 16m x (4+4)n per thread -> 1.0 B/MAC
// (fma-bound, not crossbar-bound). grid (256, 4), 49.7 KB dynamic smem.
// ============================================================================
#define GEMM_SMEM_BYTES ((2*16*132 + 2*16*256) * 4)

__global__ void __launch_bounds__(256, 1) gemm_kernel(
    const float* __restrict__ x, const float* __restrict__ w_main,
    const float* __restrict__ w_skip, float* __restrict__ out)
{
    float (*As)[16][132] = (float(*)[16][132])smem_f;                 // W^T tiles
    float (*Bs)[16][256] = (float(*)[16][256])(smem_f + 2 * 16 * 132); // outn tiles

    const int tid = threadIdx.x;
    const int b   = blockIdx.x >> 5;
    const int l0  = (blockIdx.x & 31) << 8;
    const int m0  = blockIdx.y << 7;
    const float* W = (m0 < 256) ? (w_main + m0 * 256) : (w_skip + (m0 - 256) * 256);
    const float* Bbase = g_outn + (size_t)b * CC * LL + l0;

    ull acc[16][4];
    #pragma unroll
    for (int i = 0; i < 16; i++)
        #pragma unroll
        for (int j = 0; j < 4; j++) acc[i][j] = 0ull;

    // ---- prologue: k-chunk 0 into buffer 0 ----
    #pragma unroll
    for (int it = 0; it < 2; it++) {
        int v = tid + (it << 8);
        int m = v >> 2, k0 = (v & 3) << 2;
        float4 ra = *(const float4*)(W + m * 256 + k0);
        As[0][k0 + 0][m] = ra.x; As[0][k0 + 1][m] = ra.y;
        As[0][k0 + 2][m] = ra.z; As[0][k0 + 3][m] = ra.w;
    }
    #pragma unroll
    for (int it = 0; it < 4; it++) {
        int v = tid + (it << 8);
        int k = v >> 6, n0 = (v & 63) << 2;
        *(float4*)&Bs[0][k][n0] = *(const float4*)(Bbase + (size_t)k * LL + n0);
    }
    __syncthreads();

    const int ty = tid >> 5, tx = tid & 31;
    const int mb = ty << 4, nb = tx << 2;

    for (int kt = 0; kt < 16; kt++) {
        const int cur = kt & 1;
        float4 ra[2], rb[4];
        if (kt < 15) {
            const int kc = (kt + 1) << 4;
            #pragma unroll
            for (int it = 0; it < 2; it++) {
                int v = tid + (it << 8);
                int m = v >> 2, k0 = (v & 3) << 2;
                ra[it] = *(const float4*)(W + m * 256 + kc + k0);
            }
            #pragma unroll
            for (int it = 0; it < 4; it++) {
                int v = tid + (it << 8);
                int k = v >> 6, n0 = (v & 63) << 2;
                rb[it] = *(const float4*)(Bbase + (size_t)(kc + k) * LL + n0);
            }
        }
        #pragma unroll
        for (int k = 0; k < 16; k++) {
            ulonglong2 B0 = *(const ulonglong2*)&Bs[cur][k][nb];
            ulonglong2 B1 = *(const ulonglong2*)&Bs[cur][k][128 + nb];
            ull b0 = B0.x, b1 = B0.y, b2 = B1.x, b3 = B1.y;
            #pragma unroll
            for (int ia = 0; ia < 4; ia++) {
                float4 a = *(const float4*)&As[cur][k][mb + (ia << 2)];
                ull d;
                int r = ia << 2;
                d = pk2(a.x); fma2(acc[r+0][0], d, b0); fma2(acc[r+0][1], d, b1); fma2(acc[r+0][2], d, b2); fma2(acc[r+0][3], d, b3);
                d = pk2(a.y); fma2(acc[r+1][0], d, b0); fma2(acc[r+1][1], d, b1); fma2(acc[r+1][2], d, b2); fma2(acc[r+1][3], d, b3);
                d = pk2(a.z); fma2(acc[r+2][0], d, b0); fma2(acc[r+2][1], d, b1); fma2(acc[r+2][2], d, b2); fma2(acc[r+2][3], d, b3);
                d = pk2(a.w); fma2(acc[r+3][0], d, b0); fma2(acc[r+3][1], d, b1); fma2(acc[r+3][2], d, b2); fma2(acc[r+3][3], d, b3);
            }
        }
        if (kt < 15) {
            __syncthreads();
            const int nxt = cur ^ 1;
            #pragma unroll
            for (int it = 0; it < 2; it++) {
                int v = tid + (it << 8);
                int m = v >> 2, k0 = (v & 3) << 2;
                As[nxt][k0 + 0][m] = ra[it].x; As[nxt][k0 + 1][m] = ra[it].y;
                As[nxt][k0 + 2][m] = ra[it].z; As[nxt][k0 + 3][m] = ra[it].w;
            }
            #pragma unroll
            for (int it = 0; it < 4; it++) {
                int v = tid + (it << 8);
                int k = v >> 6, n0 = (v & 63) << 2;
                *(float4*)&Bs[nxt][k][n0] = rb[it];
            }
            __syncthreads();
        }
    }

    // ---- epilogue: +x residual on main half, write both n-halves ----
    const size_t CL = (size_t)CC * LL;
    const int n = l0 + nb;
    #pragma unroll
    for (int im = 0; im < 16; im++) {
        int m = m0 + mb + im;
        float2 p0 = up2(acc[im][0]), p1 = up2(acc[im][1]);
        float2 p2 = up2(acc[im][2]), p3 = up2(acc[im][3]);
        float4 r0 = make_float4(p0.x, p0.y, p1.x, p1.y);
        float4 r1 = make_float4(p2.x, p2.y, p3.x, p3.y);
        float* dst;
        if (m < 256) {
            const float* xr = x + (size_t)b * CL + (size_t)m * LL + n;
            float4 x0 = *(const float4*)xr;
            float4 x1 = *(const float4*)(xr + 128);
            r0.x += x0.x; r0.y += x0.y; r0.z += x0.z; r0.w += x0.w;
            r1.x += x1.x; r1.y += x1.y; r1.z += x1.z; r1.w += x1.w;
            dst = out + (size_t)b * CL + (size_t)m * LL + n;
        } else {
            dst = out + (size_t)BB * CL + (size_t)b * CL + (size_t)(m - 256) * LL + n;
        }
        *(float4*)dst = r0;
        *(float4*)(dst + 128) = r1;
    }
}

// ============================================================================
extern "C" void kernel_launch(void* const* d_in, const int* in_sizes, int n_in,
                              void* d_out, int out_size) {
    const float* x        = (const float*)d_in[0];
    const float* w_reduce = (const float*)d_in[1];
    const float* w_span   = (const float*)d_in[2];
    const float* prelu_a  = (const float*)d_in[3];
    const float* ln_gamma = (const float*)d_in[4];
    const float* ln_beta  = (const float*)d_in[5];
    const float* w_main   = (const float*)d_in[6];
    const float* w_skip   = (const float*)d_in[7];
    float* out = (float*)d_out;

    static bool attr_set = false;
    if (!attr_set) {
        cudaFuncSetAttribute(front_kernel, cudaFuncAttributeMaxDynamicSharedMemorySize, FR_SMEM_BYTES);
        cudaFuncSetAttribute(gemm_kernel,  cudaFuncAttributeMaxDynamicSharedMemorySize, GEMM_SMEM_BYTES);
        attr_set = true;
    }

    prep_kernel<<<128, 256>>>(w_reduce, w_span);
    front_kernel<<<dim3(LL / TILE, BB), 512, FR_SMEM_BYTES>>>(x, prelu_a, ln_gamma, ln_beta);
    gemm_kernel<<<dim3(256, 4), 256, GEMM_SMEM_BYTES>>>(x, w_main, w_skip, out);
}

// round 6
// speedup vs baseline: 1.9739x; 1.5923x over previous
#include <cuda_runtime.h>
#include <cuda_bf16.h>
#include <cstdint>

#define CC 256
#define LL 8192
#define BB 8
#define KK 7
#define GK 112
#define TILE 64
#define SX_W 72
#define SUW 65

typedef unsigned long long ull;

// ---- device scratch ----
__device__ __nv_bfloat16 g_ah[BB * LL * CC];   // activations hi, [B*L, C]
__device__ __nv_bfloat16 g_al[BB * LL * CC];   // activations lo
__device__ __nv_bfloat16 g_wh[512 * 256];      // [w_main; w_skip] hi, [outc][k]
__device__ __nv_bfloat16 g_wl[512 * 256];      // lo
__device__ float g_wrT[256 * 64];
__device__ float g_wsT2[64 * 256];

// ---------- packed f32x2 helpers ----------
__device__ __forceinline__ ull pk2(float v) {
    ull r; unsigned u = __float_as_uint(v);
    asm("mov.b64 %0, {%1, %1};" : "=l"(r) : "r"(u));
    return r;
}
__device__ __forceinline__ void fma2(ull& d, ull a, ull b) {
    asm("fma.rn.f32x2 %0, %1, %2, %0;" : "+l"(d) : "l"(a), "l"(b));
}
__device__ __forceinline__ float2 up2(ull v) {
    unsigned lo, hi;
    asm("mov.b64 {%0, %1}, %2;" : "=r"(lo), "=r"(hi) : "l"(v));
    return make_float2(__uint_as_float(lo), __uint_as_float(hi));
}

// ---------- smem / async / mma helpers (baseline ISA only: sm_80 features) ----------
__device__ __forceinline__ uint32_t smem_u32(const void* p) {
    uint32_t a;
    asm("{ .reg .u64 t; cvta.to.shared.u64 t, %1; cvt.u32.u64 %0, t; }" : "=r"(a) : "l"(p));
    return a;
}
__device__ __forceinline__ uint32_t swz128(uint32_t off) { return off ^ ((off >> 3) & 0x70); }

__device__ __forceinline__ void cpasync16(uint32_t dst, const void* src) {
    asm volatile("cp.async.cg.shared.global [%0], [%1], 16;" :: "r"(dst), "l"(src) : "memory");
}
#define CP_COMMIT()  asm volatile("cp.async.commit_group;" ::: "memory")
#define CP_WAIT(n)   asm volatile("cp.async.wait_group %0;" :: "n"(n) : "memory")

__device__ __forceinline__ void ldsm_x4(uint32_t* r, uint32_t addr) {
    asm volatile("ldmatrix.sync.aligned.m8n8.x4.shared.b16 {%0,%1,%2,%3}, [%4];"
        : "=r"(r[0]), "=r"(r[1]), "=r"(r[2]), "=r"(r[3]) : "r"(addr));
}
__device__ __forceinline__ void mma16816(float* d, const uint32_t* a, const uint32_t* b) {
    asm volatile(
        "mma.sync.aligned.m16n8k16.row.col.f32.bf16.bf16.f32 "
        "{%0,%1,%2,%3}, {%4,%5,%6,%7}, {%8,%9}, {%0,%1,%2,%3};"
        : "+f"(d[0]), "+f"(d[1]), "+f"(d[2]), "+f"(d[3])
        : "r"(a[0]), "r"(a[1]), "r"(a[2]), "r"(a[3]), "r"(b[0]), "r"(b[1]));
}

extern __shared__ float smem_f[];

// ============================================================================
// Kernel 0: weight prep (transpose + bf16 hi/lo split)
// ============================================================================
__global__ void prep_kernel(const float* __restrict__ wr, const float* __restrict__ ws,
                            const float* __restrict__ wm, const float* __restrict__ wk) {
    int gid = blockIdx.x * 256 + threadIdx.x;            // 0..163839
    if (gid < 16384) {
        int c = gid >> 6, r = gid & 63;
        g_wrT[gid] = wr[r * 256 + c];
    } else if (gid < 32768) {
        int i2 = gid - 16384;
        int r = i2 >> 8, rem = i2 & 255;
        int kg = rem >> 4, j = rem & 15;
        g_wsT2[i2] = (j < 14) ? ws[(kg * 7 + (j >> 1)) * 64 + r] : 0.f;
    } else {
        int i = gid - 32768;                              // 0..131071
        int r = i >> 8, c = i & 255;
        float v = (r < 256) ? wm[r * 256 + c] : wk[(r - 256) * 256 + c];
        __nv_bfloat16 hi = __float2bfloat16(v);
        g_wh[i] = hi;
        g_wl[i] = __float2bfloat16(v - __bfloat162float(hi));
    }
}

// ============================================================================
// Kernel 1: fused kernel-gen + involution + PReLU + LayerNorm -> bf16 hi/lo
// ============================================================================
#define FR_SMEM_FLOATS (256*SX_W + 64*64 + GK*64 + 256*SUW + 128)
#define FR_SMEM_BYTES  (FR_SMEM_FLOATS * 4)

__global__ void __launch_bounds__(512, 1) front_kernel(
    const float* __restrict__ x, const float* __restrict__ prelu_a,
    const float* __restrict__ ln_gamma, const float* __restrict__ ln_beta)
{
    float* sx   = smem_f;
    float* sh   = sx + 256 * SX_W;
    float* sker = sh + 64 * 64;
    float* suni = sker + GK * 64;
    float* smu  = suni + 256 * SUW;
    float* srs  = smu + 64;

    const int tid = threadIdx.x;
    const int b   = blockIdx.y;
    const int l0  = blockIdx.x * TILE;
    const float* xb = x + (size_t)b * CC * LL;

    for (int idx = tid; idx < 256 * 70; idx += 512) {
        int c = idx / 70, j = idx - c * 70;
        int l = l0 - 3 + j;
        sx[c * SX_W + 1 + j] = (l >= 0 && l < LL) ? xb[c * LL + l] : 0.f;
    }
    for (int i = tid; i < 4096; i += 512)
        ((float4*)suni)[i] = ((const float4*)g_wrT)[i];
    __syncthreads();

    {
        const int r0 = (tid >> 4) << 1;
        const int t0 = (tid & 15) << 2;
        ull a00 = 0, a01 = 0, a10 = 0, a11 = 0;
        const float* xp = sx + 4 + t0;
        const float* wp = suni + r0;
        #pragma unroll 8
        for (int c = 0; c < 256; c++) {
            ulonglong2 bb = *(const ulonglong2*)(xp + c * SX_W);
            float2 aw = *(const float2*)(wp + (c << 6));
            ull d0 = pk2(aw.x), d1 = pk2(aw.y);
            fma2(a00, d0, bb.x); fma2(a01, d0, bb.y);
            fma2(a10, d1, bb.x); fma2(a11, d1, bb.y);
        }
        float2 v;
        float* o0 = sh + r0 * 64 + t0;
        float* o1 = o0 + 64;
        v = up2(a00); o0[0] = fmaxf(v.x, 0.f); o0[1] = fmaxf(v.y, 0.f);
        v = up2(a01); o0[2] = fmaxf(v.x, 0.f); o0[3] = fmaxf(v.y, 0.f);
        v = up2(a10); o1[0] = fmaxf(v.x, 0.f); o1[1] = fmaxf(v.y, 0.f);
        v = up2(a11); o1[2] = fmaxf(v.x, 0.f); o1[3] = fmaxf(v.y, 0.f);
    }
    __syncthreads();

    for (int i = tid; i < 4096; i += 512)
        ((float4*)suni)[i] = ((const float4*)g_wsT2)[i];
    __syncthreads();

    {
        const int kg = tid >> 5;
        const int t2 = (tid & 31) << 1;
        ull acc[7] = {0, 0, 0, 0, 0, 0, 0};
        const float* hp = sh + t2;
        #pragma unroll 4
        for (int r = 0; r < 64; r++) {
            ull bv = *(const ull*)(hp + (r << 6));
            const ull* w = (const ull*)(suni + (r << 8) + (kg << 4));
            #pragma unroll
            for (int i = 0; i < 7; i++) fma2(acc[i], w[i], bv);
        }
        #pragma unroll
        for (int i = 0; i < 7; i++) {
            float2 v = up2(acc[i]);
            *(float2*)(sker + (kg * 7 + i) * 64 + t2) = v;
        }
    }
    __syncthreads();

    {
        const float al = prelu_a[0];
        const int q = tid >> 4;
        const int tb = (tid & 15) << 2;
        #pragma unroll
        for (int i = 0; i < 8; i++) {
            int c  = q + 32 * i;
            int g7 = (c >> 4) * KK;
            float a0 = 0.f, a1 = 0.f, a2 = 0.f, a3 = 0.f;
            const float* xr = sx + c * SX_W + 1 + tb;
            #pragma unroll
            for (int k = 0; k < KK; k++) {
                float4 kv = *(const float4*)(sker + (g7 + k) * 64 + tb);
                a0 += kv.x * xr[k];
                a1 += kv.y * xr[k + 1];
                a2 += kv.z * xr[k + 2];
                a3 += kv.w * xr[k + 3];
            }
            float* o = suni + c * SUW + tb;
            o[0] = a0 >= 0.f ? a0 : al * a0;
            o[1] = a1 >= 0.f ? a1 : al * a1;
            o[2] = a2 >= 0.f ? a2 : al * a2;
            o[3] = a3 >= 0.f ? a3 : al * a3;
        }
    }
    __syncthreads();

    {
        int col = tid >> 3, part = tid & 7;
        float s = 0.f, s2 = 0.f;
        const float* p = suni + (part << 5) * SUW + col;
        #pragma unroll 8
        for (int cc = 0; cc < 32; cc++) { float v = p[cc * SUW]; s += v; s2 += v * v; }
        s  += __shfl_xor_sync(0xffffffffu, s, 1);
        s2 += __shfl_xor_sync(0xffffffffu, s2, 1);
        s  += __shfl_xor_sync(0xffffffffu, s, 2);
        s2 += __shfl_xor_sync(0xffffffffu, s2, 2);
        s  += __shfl_xor_sync(0xffffffffu, s, 4);
        s2 += __shfl_xor_sync(0xffffffffu, s2, 4);
        if (part == 0) {
            float mu  = s * (1.f / 256.f);
            float var = s2 * (1.f / 256.f) - mu * mu;
            smu[col] = mu;
            srs[col] = rsqrtf(var + 1e-5f);
        }
    }
    __syncthreads();

    {
        const size_t rowbase = (size_t)(b * LL + l0) * 256;
        const int c = tid & 255, thi = tid >> 8;
        const float g  = __ldg(ln_gamma + c);
        const float be = __ldg(ln_beta + c);
        #pragma unroll
        for (int it = 0; it < 32; it++) {
            int t = (it << 1) + thi;
            float v = (suni[c * SUW + t] - smu[t]) * srs[t] * g + be;
            __nv_bfloat16 hi = __float2bfloat16(v);
            size_t gi = rowbase + (size_t)t * 256 + c;
            g_ah[gi] = hi;
            g_al[gi] = __float2bfloat16(v - __bfloat162float(hi));
        }
    }
}

// ============================================================================
// Kernel 2: mma.sync bf16 split GEMM + residual.
// M = out channels (512), N = positions. CTA 128ch x 128pos, K=256 in 4x64.
// grid (4 ch-tiles fastest, 512 pos-tiles), 256 threads, 128 KB smem.
// ============================================================================
#define STAGE_B 65536   // per stage: Ah 16K | Al 16K | Bh 16K | Bl 16K
#define GM_SMEM (2 * STAGE_B)

__device__ __forceinline__ void gemm_load(uint32_t sb,
    const __nv_bfloat16* Ah, const __nv_bfloat16* Al,
    const __nv_bfloat16* Bh, const __nv_bfloat16* Bl, int kc, int tid)
{
    #pragma unroll
    for (int it = 0; it < 4; it++) {
        int idx = tid + (it << 8);
        int r = idx >> 3, j = idx & 7;
        uint32_t off = swz128((uint32_t)(r * 128 + j * 16));
        size_t so = (size_t)r * 256 + kc + j * 8;
        cpasync16(sb + off,         Ah + so);
        cpasync16(sb + 16384 + off, Al + so);
        cpasync16(sb + 32768 + off, Bh + so);
        cpasync16(sb + 49152 + off, Bl + so);
    }
    CP_COMMIT();
}

__global__ void __launch_bounds__(256, 1) gemm_kernel(
    const float* __restrict__ x, float* __restrict__ out)
{
    const uint32_t smb = smem_u32(smem_f);
    const int tid = threadIdx.x;
    const int lane = tid & 31, wid = tid >> 5;
    const int wm = wid & 1, wn = wid >> 1;     // 2 m-blocks(64ch) x 4 n-blocks(32pos)

    const int chT  = blockIdx.x;               // 0..3 (fast -> L2 reuse of activations)
    const int posT = blockIdx.y;               // 0..511
    const int b    = posT >> 6;
    const int l0   = (posT & 63) << 7;

    const __nv_bfloat16* Ah = g_wh + (size_t)(chT << 7) * 256;
    const __nv_bfloat16* Al = g_wl + (size_t)(chT << 7) * 256;
    const __nv_bfloat16* Bh = g_ah + (size_t)(b * LL + l0) * 256;
    const __nv_bfloat16* Bl = g_al + (size_t)(b * LL + l0) * 256;

    float acc[4][4][4];
    #pragma unroll
    for (int i = 0; i < 4; i++)
        #pragma unroll
        for (int j = 0; j < 4; j++)
            #pragma unroll
            for (int k = 0; k < 4; k++) acc[i][j][k] = 0.f;

    // lane-dependent ldmatrix base offsets (bytes within tile)
    uint32_t baseA[4], baseB[2];
    {
        int rowA = lane & 15, hiA = (lane >> 4) << 4;
        #pragma unroll
        for (int mi = 0; mi < 4; mi++)
            baseA[mi] = (uint32_t)((wm * 64 + mi * 16 + rowA) * 128 + hiA);
        int rowB = wn * 32 + (lane & 7) + ((lane >> 4) << 3);
        int koB  = ((lane >> 3) & 1) << 4;
        baseB[0] = (uint32_t)(rowB * 128 + koB);
        baseB[1] = baseB[0] + 16 * 128;
    }

    gemm_load(smb,           Ah, Al, Bh, Bl, 0,  tid);
    gemm_load(smb + STAGE_B, Ah, Al, Bh, Bl, 64, tid);

    #pragma unroll
    for (int kt = 0; kt < 4; kt++) {
        if (kt < 3) { CP_WAIT(1); } else { CP_WAIT(0); }
        __syncthreads();
        const uint32_t sb = smb + (kt & 1) * STAGE_B;

        #pragma unroll
        for (int ks = 0; ks < 4; ks++) {
            const uint32_t kb = ks << 5;     // 32 bytes per k16 step
            uint32_t ah[4][4], al[4][4], bh[2][4], bl[2][4];
            #pragma unroll
            for (int mi = 0; mi < 4; mi++) {
                ldsm_x4(ah[mi], sb +         swz128(baseA[mi] + kb));
                ldsm_x4(al[mi], sb + 16384 + swz128(baseA[mi] + kb));
            }
            #pragma unroll
            for (int nh = 0; nh < 2; nh++) {
                ldsm_x4(bh[nh], sb + 32768 + swz128(baseB[nh] + kb));
                ldsm_x4(bl[nh], sb + 49152 + swz128(baseB[nh] + kb));
            }
            #pragma unroll
            for (int mi = 0; mi < 4; mi++) {
                #pragma unroll
                for (int ni = 0; ni < 4; ni++) {
                    const uint32_t* bhp = &bh[ni >> 1][(ni & 1) << 1];
                    const uint32_t* blp = &bl[ni >> 1][(ni & 1) << 1];
                    mma16816(acc[mi][ni], ah[mi], bhp);
                    mma16816(acc[mi][ni], ah[mi], blp);
                    mma16816(acc[mi][ni], al[mi], bhp);
                }
            }
        }

        if (kt < 2) {
            __syncthreads();
            gemm_load(sb, Ah, Al, Bh, Bl, (kt + 2) << 6, tid);
        }
    }

    // ---- epilogue: direct coalesced stores + residual on main half ----
    const int quad = lane >> 2, qt = lane & 3;
    const size_t CL = (size_t)CC * LL;
    #pragma unroll
    for (int mi = 0; mi < 4; mi++) {
        int gch0 = (chT << 7) + wm * 64 + mi * 16 + quad;
        #pragma unroll
        for (int ni = 0; ni < 4; ni++) {
            int l = l0 + wn * 32 + ni * 8 + (qt << 1);
            #pragma unroll
            for (int hrow = 0; hrow < 2; hrow++) {
                int g = gch0 + hrow * 8;
                float v0 = acc[mi][ni][hrow * 2];
                float v1 = acc[mi][ni][hrow * 2 + 1];
                float* dst;
                if (g < 256) {
                    const float* xr = x + (size_t)b * CL + (size_t)g * LL + l;
                    v0 += xr[0]; v1 += xr[1];
                    dst = out + (size_t)b * CL + (size_t)g * LL + l;
                } else {
                    dst = out + (size_t)BB * CL + (size_t)b * CL + (size_t)(g - 256) * LL + l;
                }
                *(float2*)dst = make_float2(v0, v1);
            }
        }
    }
}

// ============================================================================
extern "C" void kernel_launch(void* const* d_in, const int* in_sizes, int n_in,
                              void* d_out, int out_size) {
    const float* x        = (const float*)d_in[0];
    const float* w_reduce = (const float*)d_in[1];
    const float* w_span   = (const float*)d_in[2];
    const float* prelu_a  = (const float*)d_in[3];
    const float* ln_gamma = (const float*)d_in[4];
    const float* ln_beta  = (const float*)d_in[5];
    const float* w_main   = (const float*)d_in[6];
    const float* w_skip   = (const float*)d_in[7];
    float* out = (float*)d_out;

    static bool attr_set = false;
    if (!attr_set) {
        cudaFuncSetAttribute(front_kernel, cudaFuncAttributeMaxDynamicSharedMemorySize, FR_SMEM_BYTES);
        cudaFuncSetAttribute(gemm_kernel,  cudaFuncAttributeMaxDynamicSharedMemorySize, GM_SMEM);
        attr_set = true;
    }

    prep_kernel<<<640, 256>>>(w_reduce, w_span, w_main, w_skip);
    front_kernel<<<dim3(LL / TILE, BB), 512, FR_SMEM_BYTES>>>(x, prelu_a, ln_gamma, ln_beta);
    gemm_kernel<<<dim3(4, 512), 256, GM_SMEM>>>(x, out);
}

// round 7
// speedup vs baseline: 2.0008x; 1.0136x over previous
#include <cuda_runtime.h>
#include <cuda_bf16.h>
#include <cstdint>

#define CC 256
#define LL 8192
#define BB 8
#define KK 7
#define GK 112
#define TILE 64
#define SX_W 72
#define SUW 65

typedef unsigned long long ull;

// ---- device scratch ----
__device__ __nv_bfloat16 g_ah[BB * LL * CC];   // activations hi, [B*L, C]
__device__ __nv_bfloat16 g_al[BB * LL * CC];   // activations lo
__device__ __nv_bfloat16 g_wh[512 * 256];      // [w_main; w_skip] hi, [outc][k]
__device__ __nv_bfloat16 g_wl[512 * 256];      // lo
__device__ float g_wrT[256 * 64];
__device__ float g_wsT2[64 * 256];

// ---------- packed f32x2 helpers ----------
__device__ __forceinline__ ull pk2(float v) {
    ull r; unsigned u = __float_as_uint(v);
    asm("mov.b64 %0, {%1, %1};" : "=l"(r) : "r"(u));
    return r;
}
__device__ __forceinline__ void fma2(ull& d, ull a, ull b) {
    asm("fma.rn.f32x2 %0, %1, %2, %0;" : "+l"(d) : "l"(a), "l"(b));
}
__device__ __forceinline__ float2 up2(ull v) {
    unsigned lo, hi;
    asm("mov.b64 {%0, %1}, %2;" : "=r"(lo), "=r"(hi) : "l"(v));
    return make_float2(__uint_as_float(lo), __uint_as_float(hi));
}

// ---------- smem / async / mma helpers (baseline ISA only) ----------
__device__ __forceinline__ uint32_t smem_u32(const void* p) {
    uint32_t a;
    asm("{ .reg .u64 t; cvta.to.shared.u64 t, %1; cvt.u32.u64 %0, t; }" : "=r"(a) : "l"(p));
    return a;
}
__device__ __forceinline__ uint32_t swz128(uint32_t off) { return off ^ ((off >> 3) & 0x70); }

__device__ __forceinline__ void cpasync16(uint32_t dst, const void* src) {
    asm volatile("cp.async.cg.shared.global [%0], [%1], 16;" :: "r"(dst), "l"(src) : "memory");
}
#define CP_COMMIT()  asm volatile("cp.async.commit_group;" ::: "memory")
#define CP_WAIT(n)   asm volatile("cp.async.wait_group %0;" :: "n"(n) : "memory")

__device__ __forceinline__ void ldsm_x4(uint32_t* r, uint32_t addr) {
    asm volatile("ldmatrix.sync.aligned.m8n8.x4.shared.b16 {%0,%1,%2,%3}, [%4];"
        : "=r"(r[0]), "=r"(r[1]), "=r"(r[2]), "=r"(r[3]) : "r"(addr));
}
__device__ __forceinline__ void mma16816(float* d, const uint32_t* a, const uint32_t* b) {
    asm volatile(
        "mma.sync.aligned.m16n8k16.row.col.f32.bf16.bf16.f32 "
        "{%0,%1,%2,%3}, {%4,%5,%6,%7}, {%8,%9}, {%0,%1,%2,%3};"
        : "+f"(d[0]), "+f"(d[1]), "+f"(d[2]), "+f"(d[3])
        : "r"(a[0]), "r"(a[1]), "r"(a[2]), "r"(a[3]), "r"(b[0]), "r"(b[1]));
}

extern __shared__ float smem_f[];

// ============================================================================
// Kernel 0: weight prep (transpose + bf16 hi/lo split)
// ============================================================================
__global__ void prep_kernel(const float* __restrict__ wr, const float* __restrict__ ws,
                            const float* __restrict__ wm, const float* __restrict__ wk) {
    int gid = blockIdx.x * 256 + threadIdx.x;            // 0..163839
    if (gid < 16384) {
        int c = gid >> 6, r = gid & 63;
        g_wrT[gid] = wr[r * 256 + c];
    } else if (gid < 32768) {
        int i2 = gid - 16384;
        int r = i2 >> 8, rem = i2 & 255;
        int kg = rem >> 4, j = rem & 15;
        g_wsT2[i2] = (j < 14) ? ws[(kg * 7 + (j >> 1)) * 64 + r] : 0.f;
    } else {
        int i = gid - 32768;                              // 0..131071
        int r = i >> 8, c = i & 255;
        float v = (r < 256) ? wm[r * 256 + c] : wk[(r - 256) * 256 + c];
        __nv_bfloat16 hi = __float2bfloat16(v);
        g_wh[i] = hi;
        g_wl[i] = __float2bfloat16(v - __bfloat162float(hi));
    }
}

// ============================================================================
// Kernel 1: fused kernel-gen + involution + PReLU + LayerNorm -> bf16 hi/lo
// (unchanged from R6 — analysis shows it's at its fp32 FFMA2/issue floor)
// ============================================================================
#define FR_SMEM_FLOATS (256*SX_W + 64*64 + GK*64 + 256*SUW + 128)
#define FR_SMEM_BYTES  (FR_SMEM_FLOATS * 4)

__global__ void __launch_bounds__(512, 1) front_kernel(
    const float* __restrict__ x, const float* __restrict__ prelu_a,
    const float* __restrict__ ln_gamma, const float* __restrict__ ln_beta)
{
    float* sx   = smem_f;
    float* sh   = sx + 256 * SX_W;
    float* sker = sh + 64 * 64;
    float* suni = sker + GK * 64;
    float* smu  = suni + 256 * SUW;
    float* srs  = smu + 64;

    const int tid = threadIdx.x;
    const int b   = blockIdx.y;
    const int l0  = blockIdx.x * TILE;
    const float* xb = x + (size_t)b * CC * LL;

    for (int idx = tid; idx < 256 * 70; idx += 512) {
        int c = idx / 70, j = idx - c * 70;
        int l = l0 - 3 + j;
        sx[c * SX_W + 1 + j] = (l >= 0 && l < LL) ? xb[c * LL + l] : 0.f;
    }
    for (int i = tid; i < 4096; i += 512)
        ((float4*)suni)[i] = ((const float4*)g_wrT)[i];
    __syncthreads();

    {
        const int r0 = (tid >> 4) << 1;
        const int t0 = (tid & 15) << 2;
        ull a00 = 0, a01 = 0, a10 = 0, a11 = 0;
        const float* xp = sx + 4 + t0;
        const float* wp = suni + r0;
        #pragma unroll 8
        for (int c = 0; c < 256; c++) {
            ulonglong2 bb = *(const ulonglong2*)(xp + c * SX_W);
            float2 aw = *(const float2*)(wp + (c << 6));
            ull d0 = pk2(aw.x), d1 = pk2(aw.y);
            fma2(a00, d0, bb.x); fma2(a01, d0, bb.y);
            fma2(a10, d1, bb.x); fma2(a11, d1, bb.y);
        }
        float2 v;
        float* o0 = sh + r0 * 64 + t0;
        float* o1 = o0 + 64;
        v = up2(a00); o0[0] = fmaxf(v.x, 0.f); o0[1] = fmaxf(v.y, 0.f);
        v = up2(a01); o0[2] = fmaxf(v.x, 0.f); o0[3] = fmaxf(v.y, 0.f);
        v = up2(a10); o1[0] = fmaxf(v.x, 0.f); o1[1] = fmaxf(v.y, 0.f);
        v = up2(a11); o1[2] = fmaxf(v.x, 0.f); o1[3] = fmaxf(v.y, 0.f);
    }
    __syncthreads();

    for (int i = tid; i < 4096; i += 512)
        ((float4*)suni)[i] = ((const float4*)g_wsT2)[i];
    __syncthreads();

    {
        const int kg = tid >> 5;
        const int t2 = (tid & 31) << 1;
        ull acc[7] = {0, 0, 0, 0, 0, 0, 0};
        const float* hp = sh + t2;
        #pragma unroll 4
        for (int r = 0; r < 64; r++) {
            ull bv = *(const ull*)(hp + (r << 6));
            const ull* w = (const ull*)(suni + (r << 8) + (kg << 4));
            #pragma unroll
            for (int i = 0; i < 7; i++) fma2(acc[i], w[i], bv);
        }
        #pragma unroll
        for (int i = 0; i < 7; i++) {
            float2 v = up2(acc[i]);
            *(float2*)(sker + (kg * 7 + i) * 64 + t2) = v;
        }
    }
    __syncthreads();

    {
        const float al = prelu_a[0];
        const int q = tid >> 4;
        const int tb = (tid & 15) << 2;
        #pragma unroll
        for (int i = 0; i < 8; i++) {
            int c  = q + 32 * i;
            int g7 = (c >> 4) * KK;
            float a0 = 0.f, a1 = 0.f, a2 = 0.f, a3 = 0.f;
            const float* xr = sx + c * SX_W + 1 + tb;
            #pragma unroll
            for (int k = 0; k < KK; k++) {
                float4 kv = *(const float4*)(sker + (g7 + k) * 64 + tb);
                a0 += kv.x * xr[k];
                a1 += kv.y * xr[k + 1];
                a2 += kv.z * xr[k + 2];
                a3 += kv.w * xr[k + 3];
            }
            float* o = suni + c * SUW + tb;
            o[0] = a0 >= 0.f ? a0 : al * a0;
            o[1] = a1 >= 0.f ? a1 : al * a1;
            o[2] = a2 >= 0.f ? a2 : al * a2;
            o[3] = a3 >= 0.f ? a3 : al * a3;
        }
    }
    __syncthreads();

    {
        int col = tid >> 3, part = tid & 7;
        float s = 0.f, s2 = 0.f;
        const float* p = suni + (part << 5) * SUW + col;
        #pragma unroll 8
        for (int cc = 0; cc < 32; cc++) { float v = p[cc * SUW]; s += v; s2 += v * v; }
        s  += __shfl_xor_sync(0xffffffffu, s, 1);
        s2 += __shfl_xor_sync(0xffffffffu, s2, 1);
        s  += __shfl_xor_sync(0xffffffffu, s, 2);
        s2 += __shfl_xor_sync(0xffffffffu, s2, 2);
        s  += __shfl_xor_sync(0xffffffffu, s, 4);
        s2 += __shfl_xor_sync(0xffffffffu, s2, 4);
        if (part == 0) {
            float mu  = s * (1.f / 256.f);
            float var = s2 * (1.f / 256.f) - mu * mu;
            smu[col] = mu;
            srs[col] = rsqrtf(var + 1e-5f);
        }
    }
    __syncthreads();

    {
        const size_t rowbase = (size_t)(b * LL + l0) * 256;
        const int c = tid & 255, thi = tid >> 8;
        const float g  = __ldg(ln_gamma + c);
        const float be = __ldg(ln_beta + c);
        #pragma unroll
        for (int it = 0; it < 32; it++) {
            int t = (it << 1) + thi;
            float v = (suni[c * SUW + t] - smu[t]) * srs[t] * g + be;
            __nv_bfloat16 hi = __float2bfloat16(v);
            size_t gi = rowbase + (size_t)t * 256 + c;
            g_ah[gi] = hi;
            g_al[gi] = __float2bfloat16(v - __bfloat162float(hi));
        }
    }
}

// ============================================================================
// Kernel 2: mma.sync bf16 split GEMM + residual.
// CTA = 128 out-channels x 256 positions, K=256 in 4x64 chunks, 2-stage.
// grid (4 ch-tiles fastest, 256 pos-tiles), 256 threads, 192 KB smem.
// Per warp: 64ch x 64pos; per k16: 16 ldsm.x4 : 96 mma (6:1).
// ============================================================================
#define STAGE_B 98304   // per stage: Ah 16K | Al 16K | Bh 32K | Bl 32K
#define GM_SMEM (2 * STAGE_B)

__device__ __forceinline__ void gemm_load(uint32_t sb,
    const __nv_bfloat16* Ah, const __nv_bfloat16* Al,
    const __nv_bfloat16* Bh, const __nv_bfloat16* Bl, int kc, int tid)
{
    // A tiles: 128 rows x 64k
    #pragma unroll
    for (int it = 0; it < 4; it++) {
        int idx = tid + (it << 8);
        int r = idx >> 3, j = idx & 7;
        uint32_t off = swz128((uint32_t)(r * 128 + j * 16));
        size_t so = (size_t)r * 256 + kc + j * 8;
        cpasync16(sb + off,         Ah + so);
        cpasync16(sb + 16384 + off, Al + so);
    }
    // B tiles: 256 rows x 64k
    #pragma unroll
    for (int it = 0; it < 8; it++) {
        int idx = tid + (it << 8);
        int r = idx >> 3, j = idx & 7;
        uint32_t off = swz128((uint32_t)(r * 128 + j * 16));
        size_t so = (size_t)r * 256 + kc + j * 8;
        cpasync16(sb + 32768 + off, Bh + so);
        cpasync16(sb + 65536 + off, Bl + so);
    }
    CP_COMMIT();
}

__global__ void __launch_bounds__(256) gemm_kernel(
    const float* __restrict__ x, float* __restrict__ out)
{
    const uint32_t smb = smem_u32(smem_f);
    const int tid = threadIdx.x;
    const int lane = tid & 31, wid = tid >> 5;
    const int wm = wid & 1, wn = wid >> 1;     // 2 m-blocks(64ch) x 4 n-blocks(64pos)

    const int chT  = blockIdx.x;               // 0..3 (fast -> L2 reuse of activations)
    const int posT = blockIdx.y;               // 0..255
    const int b    = posT >> 5;
    const int l0   = (posT & 31) << 8;

    const __nv_bfloat16* Ah = g_wh + (size_t)(chT << 7) * 256;
    const __nv_bfloat16* Al = g_wl + (size_t)(chT << 7) * 256;
    const __nv_bfloat16* Bh = g_ah + (size_t)(b * LL + l0) * 256;
    const __nv_bfloat16* Bl = g_al + (size_t)(b * LL + l0) * 256;

    float acc[4][8][4];
    #pragma unroll
    for (int i = 0; i < 4; i++)
        #pragma unroll
        for (int j = 0; j < 8; j++)
            #pragma unroll
            for (int k = 0; k < 4; k++) acc[i][j][k] = 0.f;

    // lane-dependent ldmatrix base offsets (bytes within tile)
    uint32_t baseA[4], baseB[4];
    {
        int rowA = lane & 15, hiA = (lane >> 4) << 4;
        #pragma unroll
        for (int mi = 0; mi < 4; mi++)
            baseA[mi] = (uint32_t)((wm * 64 + mi * 16 + rowA) * 128 + hiA);
        int rowB = wn * 64 + (lane & 7) + ((lane >> 4) << 3);
        int koB  = ((lane >> 3) & 1) << 4;
        #pragma unroll
        for (int nj = 0; nj < 4; nj++)
            baseB[nj] = (uint32_t)((rowB + nj * 16) * 128 + koB);
    }

    gemm_load(smb,           Ah, Al, Bh, Bl, 0,  tid);
    gemm_load(smb + STAGE_B, Ah, Al, Bh, Bl, 64, tid);

    #pragma unroll
    for (int kt = 0; kt < 4; kt++) {
        if (kt < 3) { CP_WAIT(1); } else { CP_WAIT(0); }
        __syncthreads();
        const uint32_t sb = smb + (kt & 1) * STAGE_B;

        #pragma unroll
        for (int ks = 0; ks < 4; ks++) {
            const uint32_t kb = ks << 5;     // 32 bytes per k16 step
            uint32_t ah[4][4], al[4][4], bh[4][4], bl[4][4];
            #pragma unroll
            for (int mi = 0; mi < 4; mi++) {
                ldsm_x4(ah[mi], sb +         swz128(baseA[mi] + kb));
                ldsm_x4(al[mi], sb + 16384 + swz128(baseA[mi] + kb));
            }
            #pragma unroll
            for (int nj = 0; nj < 4; nj++) {
                ldsm_x4(bh[nj], sb + 32768 + swz128(baseB[nj] + kb));
                ldsm_x4(bl[nj], sb + 65536 + swz128(baseB[nj] + kb));
            }
            #pragma unroll
            for (int mi = 0; mi < 4; mi++) {
                #pragma unroll
                for (int ni = 0; ni < 8; ni++) {
                    const uint32_t* bhp = &bh[ni >> 1][(ni & 1) << 1];
                    const uint32_t* blp = &bl[ni >> 1][(ni & 1) << 1];
                    mma16816(acc[mi][ni], ah[mi], bhp);
                    mma16816(acc[mi][ni], ah[mi], blp);
                    mma16816(acc[mi][ni], al[mi], bhp);
                }
            }
        }

        if (kt < 2) {
            __syncthreads();
            gemm_load(sb, Ah, Al, Bh, Bl, (kt + 2) << 6, tid);
        }
    }

    // ---- epilogue: coalesced-ish float2 stores + residual on main half ----
    const int quad = lane >> 2, qt = lane & 3;
    const size_t CL = (size_t)CC * LL;
    #pragma unroll
    for (int mi = 0; mi < 4; mi++) {
        int gch0 = (chT << 7) + wm * 64 + mi * 16 + quad;
        #pragma unroll
        for (int ni = 0; ni < 8; ni++) {
            int l = l0 + wn * 64 + ni * 8 + (qt << 1);
            #pragma unroll
            for (int hrow = 0; hrow < 2; hrow++) {
                int g = gch0 + hrow * 8;
                float v0 = acc[mi][ni][hrow * 2];
                float v1 = acc[mi][ni][hrow * 2 + 1];
                float* dst;
                if (g < 256) {
                    const float* xr = x + (size_t)b * CL + (size_t)g * LL + l;
                    v0 += __ldg(xr); v1 += __ldg(xr + 1);
                    dst = out + (size_t)b * CL + (size_t)g * LL + l;
                } else {
                    dst = out + (size_t)BB * CL + (size_t)b * CL + (size_t)(g - 256) * LL + l;
                }
                *(float2*)dst = make_float2(v0, v1);
            }
        }
    }
}

// ============================================================================
extern "C" void kernel_launch(void* const* d_in, const int* in_sizes, int n_in,
                              void* d_out, int out_size) {
    const float* x        = (const float*)d_in[0];
    const float* w_reduce = (const float*)d_in[1];
    const float* w_span   = (const float*)d_in[2];
    const float* prelu_a  = (const float*)d_in[3];
    const float* ln_gamma = (const float*)d_in[4];
    const float* ln_beta  = (const float*)d_in[5];
    const float* w_main   = (const float*)d_in[6];
    const float* w_skip   = (const float*)d_in[7];
    float* out = (float*)d_out;

    static bool attr_set = false;
    if (!attr_set) {
        cudaFuncSetAttribute(front_kernel, cudaFuncAttributeMaxDynamicSharedMemorySize, FR_SMEM_BYTES);
        cudaFuncSetAttribute(gemm_kernel,  cudaFuncAttributeMaxDynamicSharedMemorySize, GM_SMEM);
        attr_set = true;
    }

    prep_kernel<<<640, 256>>>(w_reduce, w_span, w_main, w_skip);
    front_kernel<<<dim3(LL / TILE, BB), 512, FR_SMEM_BYTES>>>(x, prelu_a, ln_gamma, ln_beta);
    gemm_kernel<<<dim3(4, 256), 256, GM_SMEM>>>(x, out);
}

// round 8
// speedup vs baseline: 2.0282x; 1.0137x over previous
#include <cuda_runtime.h>
#include <cuda_bf16.h>
#include <cstdint>

#define CC 256
#define LL 8192
#define BB 8
#define KK 7
#define GK 112
#define TILE 64
#define SX_W 72
#define SUW 65

typedef unsigned long long ull;

// ---- device scratch ----
__device__ __nv_bfloat16 g_ah[BB * LL * CC];   // activations hi, [B*L, C]
__device__ __nv_bfloat16 g_al[BB * LL * CC];   // activations lo
__device__ __nv_bfloat16 g_wh[512 * 256];      // [w_main; w_skip] hi, [outc][k]
__device__ __nv_bfloat16 g_wl[512 * 256];      // lo
__device__ float g_wrT[256 * 64];              // w_reduce transposed [c][r]

// ---------- packed f32x2 helpers ----------
__device__ __forceinline__ ull pk2(float v) {
    ull r; unsigned u = __float_as_uint(v);
    asm("mov.b64 %0, {%1, %1};" : "=l"(r) : "r"(u));
    return r;
}
__device__ __forceinline__ void fma2(ull& d, ull a, ull b) {
    asm("fma.rn.f32x2 %0, %1, %2, %0;" : "+l"(d) : "l"(a), "l"(b));
}
__device__ __forceinline__ float2 up2(ull v) {
    unsigned lo, hi;
    asm("mov.b64 {%0, %1}, %2;" : "=r"(lo), "=r"(hi) : "l"(v));
    return make_float2(__uint_as_float(lo), __uint_as_float(hi));
}

// ---------- smem / async / mma helpers (baseline ISA only) ----------
__device__ __forceinline__ uint32_t smem_u32(const void* p) {
    uint32_t a;
    asm("{ .reg .u64 t; cvta.to.shared.u64 t, %1; cvt.u32.u64 %0, t; }" : "=r"(a) : "l"(p));
    return a;
}
__device__ __forceinline__ uint32_t swz128(uint32_t off) { return off ^ ((off >> 3) & 0x70); }

__device__ __forceinline__ void cpasync16(uint32_t dst, const void* src) {
    asm volatile("cp.async.cg.shared.global [%0], [%1], 16;" :: "r"(dst), "l"(src) : "memory");
}
#define CP_COMMIT()  asm volatile("cp.async.commit_group;" ::: "memory")
#define CP_WAIT(n)   asm volatile("cp.async.wait_group %0;" :: "n"(n) : "memory")

__device__ __forceinline__ void ldsm_x4(uint32_t* r, uint32_t addr) {
    asm volatile("ldmatrix.sync.aligned.m8n8.x4.shared.b16 {%0,%1,%2,%3}, [%4];"
        : "=r"(r[0]), "=r"(r[1]), "=r"(r[2]), "=r"(r[3]) : "r"(addr));
}
__device__ __forceinline__ void mma16816(float* d, const uint32_t* a, const uint32_t* b) {
    asm volatile(
        "mma.sync.aligned.m16n8k16.row.col.f32.bf16.bf16.f32 "
        "{%0,%1,%2,%3}, {%4,%5,%6,%7}, {%8,%9}, {%0,%1,%2,%3};"
        : "+f"(d[0]), "+f"(d[1]), "+f"(d[2]), "+f"(d[3])
        : "r"(a[0]), "r"(a[1]), "r"(a[2]), "r"(a[3]), "r"(b[0]), "r"(b[1]));
}

extern __shared__ float smem_f[];

// ============================================================================
// Kernel 0: weight prep (wrT transpose + bf16 hi/lo split of main/skip)
// ============================================================================
__global__ void prep_kernel(const float* __restrict__ wr,
                            const float* __restrict__ wm, const float* __restrict__ wk) {
    int gid = blockIdx.x * 256 + threadIdx.x;            // 0..147455
    if (gid < 16384) {
        int c = gid >> 6, r = gid & 63;
        g_wrT[gid] = wr[r * 256 + c];
    } else {
        int i = gid - 16384;                              // 0..131071
        int r = i >> 8, c = i & 255;
        float v = (r < 256) ? wm[r * 256 + c] : wk[(r - 256) * 256 + c];
        __nv_bfloat16 hi = __float2bfloat16(v);
        g_wh[i] = hi;
        g_wl[i] = __float2bfloat16(v - __bfloat162float(hi));
    }
}

// ============================================================================
// Kernel 1: fused kernel-gen + involution + PReLU + LayerNorm -> bf16 hi/lo
// grid (128, 8), 512 threads, ~214.5 KB smem.
// h / ker GEMMs register-blocked on warps 0-3 (1.5 / ~1.1 B per MAC).
// ============================================================================
// smem float offsets
#define OFF_SX   0                       // [256][72]
#define OFF_SH   18432                   // [64][64]   (reused for LN partials)
#define OFF_SKER 22528                   // [112][64]
#define OFF_SWS  29696                   // [64][112]  w_span transposed
#define OFF_SOUT 36864                   // wrT(16384) then sout [256][65]
#define OFF_SMU  53504
#define OFF_SRS  53568
#define FR_SMEM_BYTES ((53568 + 64) * 4)

__global__ void __launch_bounds__(512, 1) front_kernel(
    const float* __restrict__ x, const float* __restrict__ w_span,
    const float* __restrict__ prelu_a,
    const float* __restrict__ ln_gamma, const float* __restrict__ ln_beta)
{
    float* sx   = smem_f + OFF_SX;
    float* sh   = smem_f + OFF_SH;
    float* sker = smem_f + OFF_SKER;
    float* sws  = smem_f + OFF_SWS;
    float* suni = smem_f + OFF_SOUT;    // wrT during phases 0-2, sout after
    float* smu  = smem_f + OFF_SMU;
    float* srs  = smem_f + OFF_SRS;

    const int tid = threadIdx.x;
    const int b   = blockIdx.y;
    const int l0  = blockIdx.x * TILE;
    const float* xb = x + (size_t)b * CC * LL;

    // ---- phase 0: load halo x, wrT, w_span^T ----
    for (int idx = tid; idx < 256 * 70; idx += 512) {
        int c = idx / 70, j = idx - c * 70;
        int l = l0 - 3 + j;
        sx[c * SX_W + 1 + j] = (l >= 0 && l < LL) ? xb[c * LL + l] : 0.f;
    }
    for (int i = tid; i < 4096; i += 512)
        ((float4*)suni)[i] = ((const float4*)g_wrT)[i];
    for (int idx = tid; idx < GK * 64; idx += 512) {
        int k = idx >> 6, r = idx & 63;
        sws[r * GK + k] = w_span[idx];
    }
    __syncthreads();

    // ---- phase 1: h = relu(Wr @ x), warps 0-3, 4r x 8t per thread ----
    if (tid < 128) {
        const int rg = tid >> 3, tg = tid & 7;
        const int r0 = rg << 2, t0 = tg << 3;
        ull a[4][4];
        #pragma unroll
        for (int i = 0; i < 4; i++)
            #pragma unroll
            for (int j = 0; j < 4; j++) a[i][j] = 0ull;

        const float* xp = sx + 4 + t0;
        const float* wp = suni + r0;
        #pragma unroll 4
        for (int c = 0; c < 256; c++) {
            ulonglong2 x01 = *(const ulonglong2*)(xp + c * SX_W);
            ulonglong2 x23 = *(const ulonglong2*)(xp + c * SX_W + 4);
            float4 w = *(const float4*)(wp + (c << 6));
            ull d;
            d = pk2(w.x); fma2(a[0][0], d, x01.x); fma2(a[0][1], d, x01.y); fma2(a[0][2], d, x23.x); fma2(a[0][3], d, x23.y);
            d = pk2(w.y); fma2(a[1][0], d, x01.x); fma2(a[1][1], d, x01.y); fma2(a[1][2], d, x23.x); fma2(a[1][3], d, x23.y);
            d = pk2(w.z); fma2(a[2][0], d, x01.x); fma2(a[2][1], d, x01.y); fma2(a[2][2], d, x23.x); fma2(a[2][3], d, x23.y);
            d = pk2(w.w); fma2(a[3][0], d, x01.x); fma2(a[3][1], d, x01.y); fma2(a[3][2], d, x23.x); fma2(a[3][3], d, x23.y);
        }
        #pragma unroll
        for (int i = 0; i < 4; i++) {
            float2 v0 = up2(a[i][0]), v1 = up2(a[i][1]);
            float2 v2 = up2(a[i][2]), v3 = up2(a[i][3]);
            float* o = sh + (r0 + i) * 64 + t0;
            *(float4*)o       = make_float4(fmaxf(v0.x,0.f), fmaxf(v0.y,0.f), fmaxf(v1.x,0.f), fmaxf(v1.y,0.f));
            *(float4*)(o + 4) = make_float4(fmaxf(v2.x,0.f), fmaxf(v2.y,0.f), fmaxf(v3.x,0.f), fmaxf(v3.y,0.f));
        }
    }
    __syncthreads();

    // ---- phase 2: ker = Ws @ h, warps 0-3, 7k x 8t per thread ----
    if (tid < 128) {
        const int kg = tid >> 3, tg = tid & 7;
        const int t0 = tg << 3;
        ull kacc[7][4];
        #pragma unroll
        for (int i = 0; i < 7; i++)
            #pragma unroll
            for (int j = 0; j < 4; j++) kacc[i][j] = 0ull;

        const float* hp = sh + t0;
        const float* wp = sws + kg * 7;
        #pragma unroll 2
        for (int r = 0; r < 64; r++) {
            ulonglong2 h01 = *(const ulonglong2*)(hp + (r << 6));
            ulonglong2 h23 = *(const ulonglong2*)(hp + (r << 6) + 4);
            const float* w = wp + r * GK;
            #pragma unroll
            for (int i = 0; i < 7; i++) {
                ull d = pk2(w[i]);
                fma2(kacc[i][0], d, h01.x); fma2(kacc[i][1], d, h01.y);
                fma2(kacc[i][2], d, h23.x); fma2(kacc[i][3], d, h23.y);
            }
        }
        #pragma unroll
        for (int i = 0; i < 7; i++) {
            float2 v0 = up2(kacc[i][0]), v1 = up2(kacc[i][1]);
            float2 v2 = up2(kacc[i][2]), v3 = up2(kacc[i][3]);
            float* o = sker + (kg * 7 + i) * 64 + t0;
            *(float4*)o       = make_float4(v0.x, v0.y, v1.x, v1.y);
            *(float4*)(o + 4) = make_float4(v2.x, v2.y, v3.x, v3.y);
        }
    }
    __syncthreads();

    // ---- phase 3: involution + PReLU -> sout (ker hoisted per group) ----
    {
        const float al = prelu_a[0];
        const int g  = tid >> 5;             // group 0..15
        const int h2 = (tid >> 4) & 1;       // channel half
        const int t0 = (tid & 15) << 2;      // 4 positions
        float4 kv[7];
        const float* kb = sker + (g * 7) * 64 + t0;
        #pragma unroll
        for (int k = 0; k < 7; k++) kv[k] = *(const float4*)(kb + (k << 6));

        const int c0 = (g << 4) + (h2 << 3);
        #pragma unroll
        for (int j = 0; j < 8; j++) {
            const int c = c0 + j;
            const float* xr = sx + c * SX_W + 1 + t0;
            float xv[10];
            #pragma unroll
            for (int i = 0; i < 10; i++) xv[i] = xr[i];
            float a0 = 0.f, a1 = 0.f, a2 = 0.f, a3 = 0.f;
            #pragma unroll
            for (int k = 0; k < 7; k++) {
                a0 += kv[k].x * xv[k];
                a1 += kv[k].y * xv[k + 1];
                a2 += kv[k].z * xv[k + 2];
                a3 += kv[k].w * xv[k + 3];
            }
            float* o = suni + c * SUW + t0;
            o[0] = a0 >= 0.f ? a0 : al * a0;
            o[1] = a1 >= 0.f ? a1 : al * a1;
            o[2] = a2 >= 0.f ? a2 : al * a2;
            o[3] = a3 >= 0.f ? a3 : al * a3;
        }
    }
    __syncthreads();

    // ---- phase 4: LayerNorm stats (conflict-free, smem partial reduce) ----
    {
        const int col = tid & 63, part = tid >> 6;      // 8 parts x 64 cols
        float s = 0.f, s2 = 0.f;
        const float* p = suni + (part << 5) * SUW + col;
        #pragma unroll 8
        for (int cc = 0; cc < 32; cc++) { float v = p[cc * SUW]; s += v; s2 += v * v; }
        sh[part * 64 + col]       = s;
        sh[512 + part * 64 + col] = s2;
    }
    __syncthreads();
    if (tid < 64) {
        float S = 0.f, S2 = 0.f;
        #pragma unroll
        for (int p = 0; p < 8; p++) { S += sh[p * 64 + tid]; S2 += sh[512 + p * 64 + tid]; }
        float mu  = S * (1.f / 256.f);
        float var = S2 * (1.f / 256.f) - mu * mu;
        smu[tid] = mu;
        srs[tid] = rsqrtf(var + 1e-5f);
    }
    __syncthreads();

    // ---- phase 5: normalize + affine -> bf16 hi/lo, position-major ----
    {
        const size_t rowbase = (size_t)(b * LL + l0) * 256;
        const int c = tid & 255, thi = tid >> 8;
        const float g  = __ldg(ln_gamma + c);
        const float be = __ldg(ln_beta + c);
        #pragma unroll
        for (int it = 0; it < 32; it++) {
            int t = (it << 1) + thi;
            float v = (suni[c * SUW + t] - smu[t]) * srs[t] * g + be;
            __nv_bfloat16 hi = __float2bfloat16(v);
            size_t gi = rowbase + (size_t)t * 256 + c;
            g_ah[gi] = hi;
            g_al[gi] = __float2bfloat16(v - __bfloat162float(hi));
        }
    }
}

// ============================================================================
// Kernel 2: mma.sync bf16 split GEMM + residual (unchanged from R7 — at HMMA floor)
// CTA = 128 out-channels x 256 positions, K=256 in 4x64 chunks, 2-stage.
// ============================================================================
#define STAGE_B 98304
#define GM_SMEM (2 * STAGE_B)

__device__ __forceinline__ void gemm_load(uint32_t sb,
    const __nv_bfloat16* Ah, const __nv_bfloat16* Al,
    const __nv_bfloat16* Bh, const __nv_bfloat16* Bl, int kc, int tid)
{
    #pragma unroll
    for (int it = 0; it < 4; it++) {
        int idx = tid + (it << 8);
        int r = idx >> 3, j = idx & 7;
        uint32_t off = swz128((uint32_t)(r * 128 + j * 16));
        size_t so = (size_t)r * 256 + kc + j * 8;
        cpasync16(sb + off,         Ah + so);
        cpasync16(sb + 16384 + off, Al + so);
    }
    #pragma unroll
    for (int it = 0; it < 8; it++) {
        int idx = tid + (it << 8);
        int r = idx >> 3, j = idx & 7;
        uint32_t off = swz128((uint32_t)(r * 128 + j * 16));
        size_t so = (size_t)r * 256 + kc + j * 8;
        cpasync16(sb + 32768 + off, Bh + so);
        cpasync16(sb + 65536 + off, Bl + so);
    }
    CP_COMMIT();
}

__global__ void __launch_bounds__(256) gemm_kernel(
    const float* __restrict__ x, float* __restrict__ out)
{
    const uint32_t smb = smem_u32(smem_f);
    const int tid = threadIdx.x;
    const int lane = tid & 31, wid = tid >> 5;
    const int wm = wid & 1, wn = wid >> 1;

    const int chT  = blockIdx.x;
    const int posT = blockIdx.y;
    const int b    = posT >> 5;
    const int l0   = (posT & 31) << 8;

    const __nv_bfloat16* Ah = g_wh + (size_t)(chT << 7) * 256;
    const __nv_bfloat16* Al = g_wl + (size_t)(chT << 7) * 256;
    const __nv_bfloat16* Bh = g_ah + (size_t)(b * LL + l0) * 256;
    const __nv_bfloat16* Bl = g_al + (size_t)(b * LL + l0) * 256;

    float acc[4][8][4];
    #pragma unroll
    for (int i = 0; i < 4; i++)
        #pragma unroll
        for (int j = 0; j < 8; j++)
            #pragma unroll
            for (int k = 0; k < 4; k++) acc[i][j][k] = 0.f;

    uint32_t baseA[4], baseB[4];
    {
        int rowA = lane & 15, hiA = (lane >> 4) << 4;
        #pragma unroll
        for (int mi = 0; mi < 4; mi++)
            baseA[mi] = (uint32_t)((wm * 64 + mi * 16 + rowA) * 128 + hiA);
        int rowB = wn * 64 + (lane & 7) + ((lane >> 4) << 3);
        int koB  = ((lane >> 3) & 1) << 4;
        #pragma unroll
        for (int nj = 0; nj < 4; nj++)
            baseB[nj] = (uint32_t)((rowB + nj * 16) * 128 + koB);
    }

    gemm_load(smb,           Ah, Al, Bh, Bl, 0,  tid);
    gemm_load(smb + STAGE_B, Ah, Al, Bh, Bl, 64, tid);

    #pragma unroll
    for (int kt = 0; kt < 4; kt++) {
        if (kt < 3) { CP_WAIT(1); } else { CP_WAIT(0); }
        __syncthreads();
        const uint32_t sb = smb + (kt & 1) * STAGE_B;

        #pragma unroll
        for (int ks = 0; ks < 4; ks++) {
            const uint32_t kb = ks << 5;
            uint32_t ah[4][4], al[4][4], bh[4][4], bl[4][4];
            #pragma unroll
            for (int mi = 0; mi < 4; mi++) {
                ldsm_x4(ah[mi], sb +         swz128(baseA[mi] + kb));
                ldsm_x4(al[mi], sb + 16384 + swz128(baseA[mi] + kb));
            }
            #pragma unroll
            for (int nj = 0; nj < 4; nj++) {
                ldsm_x4(bh[nj], sb + 32768 + swz128(baseB[nj] + kb));
                ldsm_x4(bl[nj], sb + 65536 + swz128(baseB[nj] + kb));
            }
            #pragma unroll
            for (int mi = 0; mi < 4; mi++) {
                #pragma unroll
                for (int ni = 0; ni < 8; ni++) {
                    const uint32_t* bhp = &bh[ni >> 1][(ni & 1) << 1];
                    const uint32_t* blp = &bl[ni >> 1][(ni & 1) << 1];
                    mma16816(acc[mi][ni], ah[mi], bhp);
                    mma16816(acc[mi][ni], ah[mi], blp);
                    mma16816(acc[mi][ni], al[mi], bhp);
                }
            }
        }

        if (kt < 2) {
            __syncthreads();
            gemm_load(sb, Ah, Al, Bh, Bl, (kt + 2) << 6, tid);
        }
    }

    const int quad = lane >> 2, qt = lane & 3;
    const size_t CL = (size_t)CC * LL;
    #pragma unroll
    for (int mi = 0; mi < 4; mi++) {
        int gch0 = (chT << 7) + wm * 64 + mi * 16 + quad;
        #pragma unroll
        for (int ni = 0; ni < 8; ni++) {
            int l = l0 + wn * 64 + ni * 8 + (qt << 1);
            #pragma unroll
            for (int hrow = 0; hrow < 2; hrow++) {
                int g = gch0 + hrow * 8;
                float v0 = acc[mi][ni][hrow * 2];
                float v1 = acc[mi][ni][hrow * 2 + 1];
                float* dst;
                if (g < 256) {
                    const float* xr = x + (size_t)b * CL + (size_t)g * LL + l;
                    v0 += __ldg(xr); v1 += __ldg(xr + 1);
                    dst = out + (size_t)b * CL + (size_t)g * LL + l;
                } else {
                    dst = out + (size_t)BB * CL + (size_t)b * CL + (size_t)(g - 256) * LL + l;
                }
                *(float2*)dst = make_float2(v0, v1);
            }
        }
    }
}

// ============================================================================
extern "C" void kernel_launch(void* const* d_in, const int* in_sizes, int n_in,
                              void* d_out, int out_size) {
    const float* x        = (const float*)d_in[0];
    const float* w_reduce = (const float*)d_in[1];
    const float* w_span   = (const float*)d_in[2];
    const float* prelu_a  = (const float*)d_in[3];
    const float* ln_gamma = (const float*)d_in[4];
    const float* ln_beta  = (const float*)d_in[5];
    const float* w_main   = (const float*)d_in[6];
    const float* w_skip   = (const float*)d_in[7];
    float* out = (float*)d_out;

    static bool attr_set = false;
    if (!attr_set) {
        cudaFuncSetAttribute(front_kernel, cudaFuncAttributeMaxDynamicSharedMemorySize, FR_SMEM_BYTES);
        cudaFuncSetAttribute(gemm_kernel,  cudaFuncAttributeMaxDynamicSharedMemorySize, GM_SMEM);
        attr_set = true;
    }

    prep_kernel<<<576, 256>>>(w_reduce, w_main, w_skip);
    front_kernel<<<dim3(LL / TILE, BB), 512, FR_SMEM_BYTES>>>(x, w_span, prelu_a, ln_gamma, ln_beta);
    gemm_kernel<<<dim3(4, 256), 256, GM_SMEM>>>(x, out);
}